// round 14
// baseline (speedup 1.0000x reference)
#include <cuda_runtime.h>
#include <cuda_fp16.h>
#include <math.h>
#include <stdint.h>

#define BB 4
#define TT 8192
#define DD 1024
#define HH 8
#define II 2816
#define NC 128
#define BT (BB*TT)

#define RMS_EPS 1e-6f
#define GATE_EPS 1e-5f

// ---------------- scratch ----------------
__device__ __half g_big[(size_t)BT*4096];
__device__ __half g_qh [(size_t)BT*DD];
__device__ __half g_kh [(size_t)BT*DD];
__device__ __half g_vh [(size_t)BT*DD];
__device__ float  g_h [(size_t)BT*DD];
__device__ __half g_Sh[(size_t)BB*HH*NC*128*128];
__device__ __half g_xh [(size_t)BT*DD];
__device__ __half g_oh [(size_t)BT*DD];
__device__ __half g_m1h[(size_t)BT*II];
__device__ __half g_bt [(size_t)13568*DD];
__device__ float  g_cos[TT*64];
__device__ float  g_sin[TT*64];
__device__ float  g_invf[64];

// ---------------- helpers ----------------
__device__ __forceinline__ float4 ldh4(const __half* p) {
    uint2 u = *(const uint2*)p;
    float2 f0 = __half22float2(*(__half2*)&u.x);
    float2 f1 = __half22float2(*(__half2*)&u.y);
    return make_float4(f0.x, f0.y, f1.x, f1.y);
}
__device__ __forceinline__ void mma_fp16(float* c, const uint32_t* a, const uint32_t* b) {
    asm volatile("mma.sync.aligned.m16n8k16.row.col.f32.f16.f16.f32 "
        "{%0,%1,%2,%3}, {%4,%5,%6,%7}, {%8,%9}, {%0,%1,%2,%3};"
        : "+f"(c[0]), "+f"(c[1]), "+f"(c[2]), "+f"(c[3])
        : "r"(a[0]), "r"(a[1]), "r"(a[2]), "r"(a[3]), "r"(b[0]), "r"(b[1]));
}
__device__ __forceinline__ void cpasync16(uint32_t s, const void* g) {
    asm volatile("cp.async.cg.shared.global [%0], [%1], 16;" :: "r"(s), "l"(g));
}
__device__ __forceinline__ void ldsm_x4(uint32_t* r, uint32_t addr) {
    asm volatile("ldmatrix.sync.aligned.m8n8.x4.shared.b16 {%0,%1,%2,%3}, [%4];"
        : "=r"(r[0]), "=r"(r[1]), "=r"(r[2]), "=r"(r[3]) : "r"(addr));
}
__device__ __forceinline__ void ldsm_x4_t(uint32_t* r, uint32_t addr) {
    asm volatile("ldmatrix.sync.aligned.m8n8.x4.trans.shared.b16 {%0,%1,%2,%3}, [%4];"
        : "=r"(r[0]), "=r"(r[1]), "=r"(r[2]), "=r"(r[3]) : "r"(addr));
}

// ---------------- rmsnorm -> fp16 out ----------------
__global__ void rmsnorm_kernel(const float* __restrict__ x, const float* __restrict__ w,
                               __half* __restrict__ out, float eps) {
    int row = blockIdx.x;
    const float4* xr = (const float4*)(x + (size_t)row * DD);
    float4 v = xr[threadIdx.x];
    float s = v.x * v.x + v.y * v.y + v.z * v.z + v.w * v.w;
    __shared__ float red[8];
    #pragma unroll
    for (int o = 16; o > 0; o >>= 1) s += __shfl_down_sync(0xffffffffu, s, o);
    if ((threadIdx.x & 31) == 0) red[threadIdx.x >> 5] = s;
    __syncthreads();
    if (threadIdx.x < 8) {
        s = red[threadIdx.x];
        #pragma unroll
        for (int o = 4; o > 0; o >>= 1) s += __shfl_down_sync(0xffu, s, o);
        if (threadIdx.x == 0) red[0] = s;
    }
    __syncthreads();
    float inv = rsqrtf(red[0] / (float)DD + eps);
    float4 wv = ((const float4*)w)[threadIdx.x];
    __half2* orow = (__half2*)(out + (size_t)row * DD);
    orow[threadIdx.x * 2]     = __floats2half2_rn(v.x * inv * wv.x, v.y * inv * wv.y);
    orow[threadIdx.x * 2 + 1] = __floats2half2_rn(v.z * inv * wv.z, v.w * inv * wv.w);
}

// ---------------- batched weight convert+transpose ----------------
__global__ void convT5(const float* __restrict__ w0, const float* __restrict__ w1,
                       const float* __restrict__ w2, const float* __restrict__ w3,
                       const float* __restrict__ w4, __half* __restrict__ Wt) {
    __shared__ float tile[32][33];
    const float* W = (blockIdx.z == 0) ? w0 : (blockIdx.z == 1) ? w1 :
                     (blockIdx.z == 2) ? w2 : (blockIdx.z == 3) ? w3 : w4;
    __half* dst = Wt + (size_t)blockIdx.z * 1024 * DD;
    int n0 = blockIdx.x * 32, k0 = blockIdx.y * 32;
    #pragma unroll
    for (int j = threadIdx.y; j < 32; j += 8)
        tile[j][threadIdx.x] = W[(size_t)(k0 + j) * DD + n0 + threadIdx.x];
    __syncthreads();
    #pragma unroll
    for (int j = threadIdx.y; j < 32; j += 8)
        dst[(size_t)(n0 + j) * DD + k0 + threadIdx.x] = __float2half_rn(tile[threadIdx.x][j]);
}
__global__ void convTI(const float* __restrict__ wg, const float* __restrict__ wu,
                       __half* __restrict__ Wt) {
    __shared__ float tile[32][33];
    const float* W = blockIdx.z ? wu : wg;
    int ro = blockIdx.z;
    int n0 = blockIdx.x * 32, k0 = blockIdx.y * 32;
    #pragma unroll
    for (int j = threadIdx.y; j < 32; j += 8)
        tile[j][threadIdx.x] = W[(size_t)(k0 + j) * II + n0 + threadIdx.x];
    __syncthreads();
    #pragma unroll
    for (int j = threadIdx.y; j < 32; j += 8)
        Wt[((size_t)(n0 + j) * 2 + ro) * DD + k0 + threadIdx.x] = __float2half_rn(tile[threadIdx.x][j]);
}
__global__ void convTW(const float* __restrict__ W, __half* __restrict__ Wt) {
    __shared__ float tile[32][33];
    int n0 = blockIdx.x * 32, k0 = blockIdx.y * 32;
    #pragma unroll
    for (int j = threadIdx.y; j < 32; j += 8)
        tile[j][threadIdx.x] = W[(size_t)(k0 + j) * DD + n0 + threadIdx.x];
    __syncthreads();
    #pragma unroll
    for (int j = threadIdx.y; j < 32; j += 8)
        Wt[(size_t)(n0 + j) * II + k0 + threadIdx.x] = __float2half_rn(tile[threadIdx.x][j]);
}

// ================= fp16 tensor-core GEMM =================
#define BKH 64
#define XW 36
#define AW (128*XW)
#define BW (128*XW)
#define STG (AW+BW)
#define SMEM_GEMM (3*STG*4)

template <int MODE>
__global__ __launch_bounds__(256, 2)
void hgemm_t(const __half* __restrict__ A, const __half* __restrict__ Bt,
             const float* __restrict__ R, void* __restrict__ Cv,
             int M, int N, int K) {
    extern __shared__ uint32_t smw[];

    const int tid = threadIdx.x;
    const int lane = tid & 31;
    const int w = tid >> 5;
    const int g = lane >> 2, q = lane & 3;
    const int wm = (w & 1) * 64;
    const int wn = (w >> 1) * 32;
    const int bm = blockIdx.y * 128, bn = blockIdx.x * 128;

    uint32_t sBase = (uint32_t)__cvta_generic_to_shared(smw);

    const uint32_t aLane = (uint32_t)((wm + (lane & 15)) * XW + ((lane >> 4) << 2));
    const uint32_t bLane = (uint32_t)((wn + (lane & 7) + ((lane >> 4) << 3)) * XW + (((lane >> 3) & 1) << 2));

    float acc[4][4][4];
    #pragma unroll
    for (int i = 0; i < 4; ++i)
        #pragma unroll
        for (int j = 0; j < 4; ++j)
            #pragma unroll
            for (int r = 0; r < 4; ++r) acc[i][j][r] = 0.f;

    const int ntile = K / BKH;

    auto loadTile = [&](int t, int s) {
        #pragma unroll
        for (int i = 0; i < 4; ++i) {
            int idx = i * 256 + tid;
            int row = idx >> 3, kc = (idx & 7) * 8;
            cpasync16(sBase + (uint32_t)((s * STG + row * XW) * 4 + kc * 2),
                      A + (size_t)(bm + row) * K + t * BKH + kc);
        }
        #pragma unroll
        for (int i = 0; i < 4; ++i) {
            int idx = i * 256 + tid;
            int n = idx >> 3, kc = (idx & 7) * 8;
            cpasync16(sBase + (uint32_t)((s * STG + AW + n * XW) * 4 + kc * 2),
                      Bt + (size_t)(bn + n) * K + t * BKH + kc);
        }
        asm volatile("cp.async.commit_group;");
    };

    loadTile(0, 0);
    if (ntile > 1) loadTile(1, 1);

    for (int t = 0; t < ntile; ++t) {
        int s = t % 3;
        if (t + 2 < ntile) asm volatile("cp.async.wait_group 1;");
        else               asm volatile("cp.async.wait_group 0;");
        __syncthreads();
        if (t + 2 < ntile) loadTile(t + 2, (t + 2) % 3);

        const uint32_t aOff = sBase + (uint32_t)(s * STG) * 4;
        const uint32_t bOff = sBase + (uint32_t)(s * STG + AW) * 4;
        #pragma unroll
        for (int ks = 0; ks < 4; ++ks) {
            uint32_t a[4][4], b[4][2];
            #pragma unroll
            for (int mt = 0; mt < 4; ++mt)
                ldsm_x4(a[mt], aOff + (aLane + (uint32_t)(mt * 16 * XW + ks * 8)) * 4);
            #pragma unroll
            for (int np = 0; np < 2; ++np) {
                uint32_t bb[4];
                ldsm_x4(bb, bOff + (bLane + (uint32_t)(np * 16 * XW + ks * 8)) * 4);
                b[np * 2][0]     = bb[0];
                b[np * 2][1]     = bb[1];
                b[np * 2 + 1][0] = bb[2];
                b[np * 2 + 1][1] = bb[3];
            }
            #pragma unroll
            for (int mt = 0; mt < 4; ++mt)
                #pragma unroll
                for (int nt = 0; nt < 4; ++nt)
                    mma_fp16(acc[mt][nt], a[mt], b[nt]);
        }
    }

    #pragma unroll
    for (int mt = 0; mt < 4; ++mt) {
        #pragma unroll
        for (int half = 0; half < 2; ++half) {
            int row = bm + wm + mt * 16 + g + half * 8;
            #pragma unroll
            for (int nt = 0; nt < 4; ++nt) {
                float vx = acc[mt][nt][half * 2 + 0];
                float vy = acc[mt][nt][half * 2 + 1];
                if (MODE == 0) {
                    int col = bn + wn + nt * 8 + q * 2;
                    size_t off = (size_t)row * N + col;
                    float* C = (float*)Cv;
                    float2 v2;
                    v2.x = vx; v2.y = vy;
                    if (R) {
                        const float2 rr = *(const float2*)(R + off);
                        v2.x += rr.x; v2.y += rr.y;
                    }
                    *(float2*)(C + off) = v2;
                } else if (MODE == 1) {
                    int col = bn + wn + nt * 8 + q * 2;
                    __half2* C = (__half2*)Cv;
                    C[((size_t)row * N + col) >> 1] = __floats2half2_rn(vx, vy);
                } else {
                    int oc = (bn + wn) / 2 + nt * 4 + q;
                    float r = (vx / (1.f + expf(-vx))) * vy;
                    __half* C = (__half*)Cv;
                    C[(size_t)row * (N >> 1) + oc] = __float2half_rn(r);
                }
            }
        }
    }
}

// ---------------- conv(K=4)+silu+RoPE fused (q,k path) ----------------
__global__ void conv_silu_rope_kernel(const __half* __restrict__ x, const float* __restrict__ w,
                                      __half* __restrict__ y) {
    int idx = blockIdx.x * 256 + threadIdx.x;
    int j4 = idx & 15;
    int h  = (idx >> 4) & 7;
    int t4 = (idx >> 7) & 2047;
    int b  = idx >> 18;
    const float4* w4 = (const float4*)w;
    int d1 = h * 128 + j4 * 4;
    float4 wa[4], wb[4];
    #pragma unroll
    for (int r = 0; r < 4; ++r) { wa[r] = w4[d1 + r]; wb[r] = w4[d1 + 64 + r]; }
    int t0 = t4 * 4;
    float4 xv1[7], xv2[7];
    #pragma unroll
    for (int j = 0; j < 7; ++j) {
        int tt = t0 - 3 + j;
        if (tt >= 0) {
            const __half* p = x + ((size_t)(b * TT + tt)) * 4096 + d1;
            xv1[j] = ldh4(p);
            xv2[j] = ldh4(p + 64);
        } else {
            xv1[j] = make_float4(0.f, 0.f, 0.f, 0.f);
            xv2[j] = make_float4(0.f, 0.f, 0.f, 0.f);
        }
    }
    const float4* cos4 = (const float4*)g_cos;
    const float4* sin4 = (const float4*)g_sin;
    __half2* y2 = (__half2*)y;
    #pragma unroll
    for (int i = 0; i < 4; ++i) {
        float4 a1, a2;
        a1.x = xv1[i].x * wa[0].x + xv1[i+1].x * wa[0].y + xv1[i+2].x * wa[0].z + xv1[i+3].x * wa[0].w;
        a1.y = xv1[i].y * wa[1].x + xv1[i+1].y * wa[1].y + xv1[i+2].y * wa[1].z + xv1[i+3].y * wa[1].w;
        a1.z = xv1[i].z * wa[2].x + xv1[i+1].z * wa[2].y + xv1[i+2].z * wa[2].z + xv1[i+3].z * wa[2].w;
        a1.w = xv1[i].w * wa[3].x + xv1[i+1].w * wa[3].y + xv1[i+2].w * wa[3].z + xv1[i+3].w * wa[3].w;
        a2.x = xv2[i].x * wb[0].x + xv2[i+1].x * wb[0].y + xv2[i+2].x * wb[0].z + xv2[i+3].x * wb[0].w;
        a2.y = xv2[i].y * wb[1].x + xv2[i+1].y * wb[1].y + xv2[i+2].y * wb[1].z + xv2[i+3].y * wb[1].w;
        a2.z = xv2[i].z * wb[2].x + xv2[i+1].z * wb[2].y + xv2[i+2].z * wb[2].z + xv2[i+3].z * wb[2].w;
        a2.w = xv2[i].w * wb[3].x + xv2[i+1].w * wb[3].y + xv2[i+2].w * wb[3].z + xv2[i+3].w * wb[3].w;
        a1.x /= (1.f + expf(-a1.x)); a1.y /= (1.f + expf(-a1.y));
        a1.z /= (1.f + expf(-a1.z)); a1.w /= (1.f + expf(-a1.w));
        a2.x /= (1.f + expf(-a2.x)); a2.y /= (1.f + expf(-a2.y));
        a2.z /= (1.f + expf(-a2.z)); a2.w /= (1.f + expf(-a2.w));
        int t = t0 + i;
        float4 c = cos4[t * 16 + j4];
        float4 s = sin4[t * 16 + j4];
        float4 o1, o2;
        o1.x = a1.x * c.x - a2.x * s.x;  o2.x = a1.x * s.x + a2.x * c.x;
        o1.y = a1.y * c.y - a2.y * s.y;  o2.y = a1.y * s.y + a2.y * c.y;
        o1.z = a1.z * c.z - a2.z * s.z;  o2.z = a1.z * s.z + a2.z * c.z;
        o1.w = a1.w * c.w - a2.w * s.w;  o2.w = a1.w * s.w + a2.w * c.w;
        size_t base1 = (((size_t)(b * TT + t)) * DD + d1) >> 1;
        y2[base1]      = __floats2half2_rn(o1.x, o1.y);
        y2[base1 + 1]  = __floats2half2_rn(o1.z, o1.w);
        y2[base1 + 32] = __floats2half2_rn(o2.x, o2.y);
        y2[base1 + 33] = __floats2half2_rn(o2.z, o2.w);
    }
}

// ---------------- conv(K=4)+silu (v path) ----------------
__global__ void conv_silu_h_kernel(const __half* __restrict__ x, const float* __restrict__ w,
                                   __half* __restrict__ y) {
    int idx = blockIdx.x * 256 + threadIdx.x;
    int d4 = idx & 255;
    int rest = idx >> 8;
    int t4 = rest & (TT / 4 - 1);
    int b = rest >> 11;
    const float4* w4 = (const float4*)w;
    float4 wr0 = w4[d4 * 4 + 0], wr1 = w4[d4 * 4 + 1];
    float4 wr2 = w4[d4 * 4 + 2], wr3 = w4[d4 * 4 + 3];
    int t0 = t4 * 4;
    float4 xv[7];
    #pragma unroll
    for (int j = 0; j < 7; ++j) {
        int tt = t0 - 3 + j;
        xv[j] = (tt >= 0) ? ldh4(x + ((size_t)(b * TT + tt)) * 4096 + d4 * 4)
                          : make_float4(0.f, 0.f, 0.f, 0.f);
    }
    __half2* y2 = (__half2*)y;
    #pragma unroll
    for (int i = 0; i < 4; ++i) {
        float4 a;
        a.x = xv[i].x * wr0.x + xv[i+1].x * wr0.y + xv[i+2].x * wr0.z + xv[i+3].x * wr0.w;
        a.y = xv[i].y * wr1.x + xv[i+1].y * wr1.y + xv[i+2].y * wr1.z + xv[i+3].y * wr1.w;
        a.z = xv[i].z * wr2.x + xv[i+1].z * wr2.y + xv[i+2].z * wr2.z + xv[i+3].z * wr2.w;
        a.w = xv[i].w * wr3.x + xv[i+1].w * wr3.y + xv[i+2].w * wr3.z + xv[i+3].w * wr3.w;
        a.x /= (1.f + expf(-a.x)); a.y /= (1.f + expf(-a.y));
        a.z /= (1.f + expf(-a.z)); a.w /= (1.f + expf(-a.w));
        size_t bh = ((size_t)(b * TT + t0 + i)) * 512 + d4 * 2;
        y2[bh]     = __floats2half2_rn(a.x, a.y);
        y2[bh + 1] = __floats2half2_rn(a.z, a.w);
    }
}

// ---------------- RoPE tables (cheap FP64: only range reduction) ----------------
__global__ void rope_invf_kernel() {
    int j = threadIdx.x;
    if (j < 64) g_invf[j] = (float)(1.0 / pow(10000.0, (double)j / 64.0));
}
__global__ void rope_table_kernel() {
    int idx = blockIdx.x * 256 + threadIdx.x;
    if (idx >= TT * 64) return;
    int t = idx >> 6, j = idx & 63;
    float f = (float)t * g_invf[j];                 // fp32 phase, same rounding as reference
    double d = (double)f;
    double n = floor(d * 0.15915494309189535);      // 1/(2*pi)
    float r = (float)(d - n * 6.283185307179586);   // reduced to [0, 2*pi)
    float s, c;
    __sincosf(r, &s, &c);
    g_cos[idx] = c;
    g_sin[idx] = s;
}

// ================= retention phase 1 (HMMA): S = (k*dec)^T @ v =================
#define RSTR 136
#define SMEM_P1 ((64*RSTR + 64*RSTR) * 2)
__global__ __launch_bounds__(256, 2)
void ret_phase1(const __half* __restrict__ k, const __half* __restrict__ v,
                __half* __restrict__ S) {
    extern __shared__ __half smh[];
    __half* ks = smh;
    __half* vs = smh + 64 * RSTR;
    int c = blockIdx.x, h = blockIdx.y, b = blockIdx.z;
    float gamma = 1.f - exp2f(-5.f - (float)h);
    float lg = logf(gamma);
    int tid = threadIdx.x, lane = tid & 31, w = tid >> 5;
    int g = lane >> 2, q = lane & 3;
    uint32_t sk = (uint32_t)__cvta_generic_to_shared(ks);
    uint32_t sv = (uint32_t)__cvta_generic_to_shared(vs);

    #pragma unroll
    for (int it = 0; it < 4; ++it) {
        int x = it * 256 + tid;
        int row = x >> 4, ch = x & 15;
        cpasync16(sv + (uint32_t)(row * RSTR + ch * 8) * 2,
                  v + ((size_t)(b * TT + c * 64 + row) * DD + h * 128 + ch * 8));
    }
    asm volatile("cp.async.commit_group;");
    const __half2* k2 = (const __half2*)k;
    for (int x = tid; x < 4096; x += 256) {
        int row = x >> 6, d2 = x & 63;
        float dec = expf(lg * (float)(63 - row));
        float2 kf = __half22float2(k2[((size_t)(b * TT + c * 64 + row) * DD + h * 128) / 2 + d2]);
        *(__half2*)(ks + row * RSTR + d2 * 2) = __floats2half2_rn(kf.x * dec, kf.y * dec);
    }
    asm volatile("cp.async.wait_group 0;");
    __syncthreads();

    int m0 = (w & 3) * 32;
    int e0w = (w >> 2) * 64;
    float acc[2][8][4];
    #pragma unroll
    for (int i = 0; i < 2; ++i)
        #pragma unroll
        for (int j = 0; j < 8; ++j)
            #pragma unroll
            for (int r = 0; r < 4; ++r) acc[i][j][r] = 0.f;

    int aRow = (lane & 7) + ((lane >> 4) << 3);
    int aCol = ((lane >> 3) & 1) << 3;
    int bRow = (lane & 7) + (((lane >> 3) & 1) << 3);
    int bCol = (lane >> 4) << 3;

    #pragma unroll
    for (int kt = 0; kt < 4; ++kt) {
        int j0 = kt * 16;
        uint32_t a[2][4];
        #pragma unroll
        for (int mt = 0; mt < 2; ++mt)
            ldsm_x4_t(a[mt], sk + (uint32_t)((j0 + aRow) * RSTR + m0 + mt * 16 + aCol) * 2);
        #pragma unroll
        for (int np = 0; np < 4; ++np) {
            uint32_t bb[4];
            ldsm_x4_t(bb, sv + (uint32_t)((j0 + bRow) * RSTR + e0w + np * 16 + bCol) * 2);
            #pragma unroll
            for (int mt = 0; mt < 2; ++mt) {
                mma_fp16(acc[mt][np * 2],     a[mt], bb);
                mma_fp16(acc[mt][np * 2 + 1], a[mt], bb + 2);
            }
        }
    }

    size_t sb = (((size_t)(b * HH + h)) * NC + c) * 16384;
    __half2* S2 = (__half2*)S;
    #pragma unroll
    for (int mt = 0; mt < 2; ++mt) {
        #pragma unroll
        for (int nt = 0; nt < 8; ++nt) {
            int e = e0w + nt * 8 + q * 2;
            int d1 = m0 + mt * 16 + g;
            S2[(sb + (size_t)d1 * 128 + e) >> 1]       = __floats2half2_rn(acc[mt][nt][0], acc[mt][nt][1]);
            S2[(sb + (size_t)(d1 + 8) * 128 + e) >> 1] = __floats2half2_rn(acc[mt][nt][2], acc[mt][nt][3]);
        }
    }
}

// ---------------- retention phase 2: parallel exclusive scan (half2) ----------------
__global__ void ret_scan(__half* __restrict__ S) {
    int bh = blockIdx.x >> 5;
    int pairIdx = ((blockIdx.x & 31) << 8) + threadIdx.x;
    int h = bh & 7;
    float gamma = 1.f - exp2f(-5.f - (float)h);
    float cdec = expf(logf(gamma) * 64.f);
    float2 carry = make_float2(0.f, 0.f);
    __half2* S2 = (__half2*)S;
    size_t base = (size_t)bh * NC * 8192 + pairIdx;
    for (int c = 0; c < NC; ++c) {
        size_t idx = base + (size_t)c * 8192;
        float2 loc = __half22float2(S2[idx]);
        S2[idx] = __floats2half2_rn(carry.x, carry.y);
        carry.x = carry.x * cdec + loc.x;
        carry.y = carry.y * cdec + loc.y;
    }
}

// ================= retention phase 3 (HMMA) + fused gate =================
#define ASTR3 72
#define SMEM_P3 ((3*64*RSTR + 64*ASTR3) * 2 + 512)
__global__ __launch_bounds__(256, 2)
void ret_phase3(const __half* __restrict__ q, const __half* __restrict__ k,
                const __half* __restrict__ v, const __half* __restrict__ S,
                const __half* __restrict__ gbig, const float* __restrict__ gnw,
                __half* __restrict__ oh) {
    extern __shared__ __half smh[];
    __half* qs  = smh;
    __half* ksb = smh + 64 * RSTR;
    __half* vsb = smh + 2 * 64 * RSTR;
    __half* ats = smh + 3 * 64 * RSTR;
    float*  rn  = (float*)(smh + 3 * 64 * RSTR + 64 * ASTR3);
    int c = blockIdx.x, h = blockIdx.y, b = blockIdx.z;
    float gamma = 1.f - exp2f(-5.f - (float)h);
    float lg = logf(gamma);
    const float scale = 0.08838834764831845f;
    int tid = threadIdx.x, lane = tid & 31, w = tid >> 5;
    int g = lane >> 2, qq = lane & 3;
    uint32_t sq = (uint32_t)__cvta_generic_to_shared(qs);
    uint32_t sk = (uint32_t)__cvta_generic_to_shared(ksb);
    uint32_t sv = (uint32_t)__cvta_generic_to_shared(vsb);
    uint32_t sa = (uint32_t)__cvta_generic_to_shared(ats);

    #pragma unroll
    for (int it = 0; it < 4; ++it) {
        int x = it * 256 + tid;
        int row = x >> 4, ch = x & 15;
        size_t gg = (size_t)(b * TT + c * 64 + row) * DD + h * 128 + ch * 8;
        uint32_t off = (uint32_t)(row * RSTR + ch * 8) * 2;
        cpasync16(sq + off, q + gg);
        cpasync16(sk + off, k + gg);
        cpasync16(sv + off, v + gg);
    }
    asm volatile("cp.async.commit_group;");
    asm volatile("cp.async.wait_group 0;");
    __syncthreads();

    const int mt = w & 3;
    const int m0 = mt * 16;
    const int eh = w >> 2;
    size_t sbg = (((size_t)(b * HH + h)) * NC + c) * 16384;

    int aRow = m0 + (lane & 15);
    int aCol = (lane >> 4) << 3;
    int bRowN = (lane & 7) + ((lane >> 4) << 3);
    int bColN = ((lane >> 3) & 1) << 3;
    int tRow = (lane & 7) + (((lane >> 3) & 1) << 3);
    int tCol = (lane >> 4) << 3;

    // Step A: att = q @ k^T
    {
        int n0 = eh * 32;
        float accT[4][4];
        #pragma unroll
        for (int i = 0; i < 4; ++i)
            #pragma unroll
            for (int r = 0; r < 4; ++r) accT[i][r] = 0.f;
        #pragma unroll
        for (int kt = 0; kt < 8; ++kt) {
            uint32_t a[4];
            ldsm_x4(a, sq + (uint32_t)(aRow * RSTR + aCol + kt * 16) * 2);
            #pragma unroll
            for (int np = 0; np < 2; ++np) {
                uint32_t bb[4];
                ldsm_x4(bb, sk + (uint32_t)((n0 + np * 16 + bRowN) * RSTR + bColN + kt * 16) * 2);
                mma_fp16(accT[np * 2],     a, bb);
                mma_fp16(accT[np * 2 + 1], a, bb + 2);
            }
        }
        #pragma unroll
        for (int nt = 0; nt < 4; ++nt) {
            int j0 = n0 + nt * 8 + qq * 2;
            int i1 = m0 + g, i2 = i1 + 8;
            float f0 = (i1 >= j0)     ? scale * expf(lg * (float)(i1 - j0))     : 0.f;
            float f1 = (i1 >= j0 + 1) ? scale * expf(lg * (float)(i1 - j0 - 1)) : 0.f;
            float f2 = (i2 >= j0)     ? scale * expf(lg * (float)(i2 - j0))     : 0.f;
            float f3 = (i2 >= j0 + 1) ? scale * expf(lg * (float)(i2 - j0 - 1)) : 0.f;
            *(__half2*)(ats + i1 * ASTR3 + j0) = __floats2half2_rn(accT[nt][0] * f0, accT[nt][1] * f1);
            *(__half2*)(ats + i2 * ASTR3 + j0) = __floats2half2_rn(accT[nt][2] * f2, accT[nt][3] * f3);
        }
    }
    __syncthreads();

    #pragma unroll
    for (int it = 0; it < 4; ++it) {
        int x = it * 256 + tid;
        int row = x >> 4, ch = x & 15;
        cpasync16(sk + (uint32_t)(row * RSTR + ch * 8) * 2, S + sbg + (size_t)row * 128 + ch * 8);
    }
    asm volatile("cp.async.commit_group;");

    // Step B: o1 = att @ v
    const int e0w = eh * 64;
    float accA[8][4];
    #pragma unroll
    for (int i = 0; i < 8; ++i)
        #pragma unroll
        for (int r = 0; r < 4; ++r) accA[i][r] = 0.f;
    #pragma unroll
    for (int kt = 0; kt < 4; ++kt) {
        int j0 = kt * 16;
        uint32_t a[4];
        ldsm_x4(a, sa + (uint32_t)(aRow * ASTR3 + aCol + kt * 16) * 2);
        #pragma unroll
        for (int np = 0; np < 4; ++np) {
            uint32_t bb[4];
            ldsm_x4_t(bb, sv + (uint32_t)((j0 + tRow) * RSTR + e0w + np * 16 + tCol) * 2);
            mma_fp16(accA[np * 2],     a, bb);
            mma_fp16(accA[np * 2 + 1], a, bb + 2);
        }
    }
    asm volatile("cp.async.wait_group 0;");
    __syncthreads();

    #pragma unroll
    for (int it = 0; it < 4; ++it) {
        int x = it * 256 + tid;
        int row = x >> 4, ch = x & 15;
        cpasync16(sv + (uint32_t)(row * RSTR + ch * 8) * 2, S + sbg + (size_t)(64 + row) * 128 + ch * 8);
    }
    asm volatile("cp.async.commit_group;");

    // Step C1: accB += q @ S[0:64]
    float accB[8][4];
    #pragma unroll
    for (int i = 0; i < 8; ++i)
        #pragma unroll
        for (int r = 0; r < 4; ++r) accB[i][r] = 0.f;
    #pragma unroll
    for (int kt = 0; kt < 4; ++kt) {
        int d0 = kt * 16;
        uint32_t a[4];
        ldsm_x4(a, sq + (uint32_t)(aRow * RSTR + aCol + kt * 16) * 2);
        #pragma unroll
        for (int np = 0; np < 4; ++np) {
            uint32_t bb[4];
            ldsm_x4_t(bb, sk + (uint32_t)((d0 + tRow) * RSTR + e0w + np * 16 + tCol) * 2);
            mma_fp16(accB[np * 2],     a, bb);
            mma_fp16(accB[np * 2 + 1], a, bb + 2);
        }
    }
    asm volatile("cp.async.wait_group 0;");
    __syncthreads();

    // Step C2: accB += q @ S[64:128]
    #pragma unroll
    for (int kt = 4; kt < 8; ++kt) {
        int d0 = (kt - 4) * 16;
        uint32_t a[4];
        ldsm_x4(a, sq + (uint32_t)(aRow * RSTR + aCol + kt * 16) * 2);
        #pragma unroll
        for (int np = 0; np < 4; ++np) {
            uint32_t bb[4];
            ldsm_x4_t(bb, sv + (uint32_t)((d0 + tRow) * RSTR + e0w + np * 16 + tCol) * 2);
            mma_fp16(accB[np * 2],     a, bb);
            mma_fp16(accB[np * 2 + 1], a, bb + 2);
        }
    }

    // combine + fused rmsnorm(128) * gnw * silu(g) -> fp16 oh
    int i1 = m0 + g;
    int i2 = i1 + 8;
    float cf1 = scale * expf(lg * (float)(i1 + 1));
    float cf2 = scale * expf(lg * (float)(i1 + 9));
    float ss1 = 0.f, ss2 = 0.f;
    #pragma unroll
    for (int nt = 0; nt < 8; ++nt) {
        accA[nt][0] += cf1 * accB[nt][0];
        accA[nt][1] += cf1 * accB[nt][1];
        accA[nt][2] += cf2 * accB[nt][2];
        accA[nt][3] += cf2 * accB[nt][3];
        ss1 += accA[nt][0] * accA[nt][0] + accA[nt][1] * accA[nt][1];
        ss2 += accA[nt][2] * accA[nt][2] + accA[nt][3] * accA[nt][3];
    }
    ss1 += __shfl_xor_sync(0xffffffffu, ss1, 1);
    ss1 += __shfl_xor_sync(0xffffffffu, ss1, 2);
    ss2 += __shfl_xor_sync(0xffffffffu, ss2, 1);
    ss2 += __shfl_xor_sync(0xffffffffu, ss2, 2);
    if (qq == 0) { rn[eh * 64 + i1] = ss1; rn[eh * 64 + i2] = ss2; }
    __syncthreads();
    float inv1 = rsqrtf((rn[i1] + rn[64 + i1]) * 0.0078125f + GATE_EPS);
    float inv2 = rsqrtf((rn[i2] + rn[64 + i2]) * 0.0078125f + GATE_EPS);

    size_t r1 = (size_t)(b * TT + c * 64 + i1);
    size_t r2 = r1 + 8;
    __half2* dst = (__half2*)oh;
    #pragma unroll
    for (int nt = 0; nt < 8; ++nt) {
        int e = e0w + nt * 8 + qq * 2;
        float2 gw = *(const float2*)(gnw + e);
        float2 g1 = __half22float2(*(const __half2*)(gbig + r1 * 4096 + 3072 + h * 128 + e));
        float2 g2 = __half22float2(*(const __half2*)(gbig + r2 * 4096 + 3072 + h * 128 + e));
        float o1x = accA[nt][0] * inv1 * gw.x * (g1.x / (1.f + expf(-g1.x)));
        float o1y = accA[nt][1] * inv1 * gw.y * (g1.y / (1.f + expf(-g1.y)));
        float o2x = accA[nt][2] * inv2 * gw.x * (g2.x / (1.f + expf(-g2.x)));
        float o2y = accA[nt][3] * inv2 * gw.y * (g2.y / (1.f + expf(-g2.y)));
        dst[(r1 * 1024 + h * 128 + e) >> 1] = __floats2half2_rn(o1x, o1y);
        dst[(r2 * 1024 + h * 128 + e) >> 1] = __floats2half2_rn(o2x, o2y);
    }
}

// ---------------- launch ----------------
extern "C" void kernel_launch(void* const* d_in, const int* in_sizes, int n_in,
                              void* d_out, int out_size) {
    const float* hs    = (const float*)d_in[0];
    const float* ln1   = (const float*)d_in[1];
    const float* ln2   = (const float*)d_in[2];
    const float* wq    = (const float*)d_in[3];
    const float* wk    = (const float*)d_in[4];
    const float* wv    = (const float*)d_in[5];
    const float* wg    = (const float*)d_in[6];
    const float* wo    = (const float*)d_in[7];
    const float* cq    = (const float*)d_in[8];
    const float* ck    = (const float*)d_in[9];
    const float* cv    = (const float*)d_in[10];
    const float* gn    = (const float*)d_in[11];
    const float* wgate = (const float*)d_in[12];
    const float* wup   = (const float*)d_in[13];
    const float* wdown = (const float*)d_in[14];
    float* out = (float*)d_out;

    cudaFuncSetAttribute(hgemm_t<0>, cudaFuncAttributeMaxDynamicSharedMemorySize, SMEM_GEMM);
    cudaFuncSetAttribute(hgemm_t<1>, cudaFuncAttributeMaxDynamicSharedMemorySize, SMEM_GEMM);
    cudaFuncSetAttribute(hgemm_t<2>, cudaFuncAttributeMaxDynamicSharedMemorySize, SMEM_GEMM);
    cudaFuncSetAttribute(ret_phase1, cudaFuncAttributeMaxDynamicSharedMemorySize, SMEM_P1);
    cudaFuncSetAttribute(ret_phase3, cudaFuncAttributeMaxDynamicSharedMemorySize, SMEM_P3);

    float *hbuf;
    __half *big, *qh, *kh, *vh, *Sh, *xh, *oh, *m1h, *bt;
    cudaGetSymbolAddress((void**)&big, g_big);
    cudaGetSymbolAddress((void**)&qh,  g_qh);
    cudaGetSymbolAddress((void**)&kh,  g_kh);
    cudaGetSymbolAddress((void**)&vh,  g_vh);
    cudaGetSymbolAddress((void**)&hbuf, g_h);
    cudaGetSymbolAddress((void**)&Sh,  g_Sh);
    cudaGetSymbolAddress((void**)&xh,  g_xh);
    cudaGetSymbolAddress((void**)&oh,  g_oh);
    cudaGetSymbolAddress((void**)&m1h, g_m1h);
    cudaGetSymbolAddress((void**)&bt,  g_bt);

    __half* bt_wo   = bt + (size_t)4096 * DD;
    __half* bt_mlp  = bt + (size_t)5120 * DD;
    __half* bt_down = bt + (size_t)10752 * DD;

    dim3 tb(32, 8);
    convT5<<<dim3(32, 32, 5), tb>>>(wq, wk, wv, wg, wo, bt);
    convTI<<<dim3(88, 32, 2), tb>>>(wgate, wup, bt_mlp);
    convTW<<<dim3(32, 88, 1), tb>>>(wdown, bt_down);

    rope_invf_kernel<<<1, 64>>>();
    rope_table_kernel<<<(TT * 64 + 255) / 256, 256>>>();
    rmsnorm_kernel<<<BT, 256>>>(hs, ln1, xh, RMS_EPS);

    dim3 gQKVG(4096 / 128, BT / 128);
    hgemm_t<1><<<gQKVG, 256, SMEM_GEMM>>>(xh, bt, nullptr, big, BT, 4096, DD);

    const int crblocks = (BB * (TT / 4) * HH * 16) / 256;
    const int cvblocks = BB * TT / 4;
    conv_silu_rope_kernel<<<crblocks, 256>>>(big,        cq, qh);
    conv_silu_rope_kernel<<<crblocks, 256>>>(big + 1024, ck, kh);
    conv_silu_h_kernel<<<cvblocks, 256>>>(big + 2048, cv, vh);

    dim3 gc(NC, HH, BB);
    ret_phase1<<<gc, 256, SMEM_P1>>>(kh, vh, Sh);
    ret_scan<<<BB * HH * 32, 256>>>(Sh);
    ret_phase3<<<gc, 256, SMEM_P3>>>(qh, kh, vh, Sh, big, gn, oh);

    dim3 gD(DD / 128, BT / 128);
    hgemm_t<0><<<gD, 256, SMEM_GEMM>>>(oh, bt_wo, hs, hbuf, BT, DD, DD);

    rmsnorm_kernel<<<BT, 256>>>(hbuf, ln2, xh, RMS_EPS);
    dim3 gMLP(5632 / 128, BT / 128);
    hgemm_t<2><<<gMLP, 256, SMEM_GEMM>>>(xh, bt_mlp, nullptr, m1h, BT, 5632, DD);
    hgemm_t<0><<<gD, 256, SMEM_GEMM>>>(m1h, bt_down, hbuf, out, BT, DD, II);
}

// round 15
// speedup vs baseline: 1.0044x; 1.0044x over previous
#include <cuda_runtime.h>
#include <cuda_fp16.h>
#include <math.h>
#include <stdint.h>

#define BB 4
#define TT 8192
#define DD 1024
#define HH 8
#define II 2816
#define NC 128
#define BT (BB*TT)

#define RMS_EPS 1e-6f
#define GATE_EPS 1e-5f

// ---------------- scratch ----------------
__device__ __half g_big[(size_t)BT*4096];
__device__ __half g_qh [(size_t)BT*DD];
__device__ __half g_kh [(size_t)BT*DD];
__device__ __half g_vh [(size_t)BT*DD];
__device__ float  g_h [(size_t)BT*DD];
__device__ __half g_Sh[(size_t)BB*HH*NC*128*128];
__device__ __half g_xh [(size_t)BT*DD];
__device__ __half g_oh [(size_t)BT*DD];
__device__ __half g_m1h[(size_t)BT*II];
__device__ __half g_bt [(size_t)13568*DD];
__device__ float  g_cos[TT*64];
__device__ float  g_sin[TT*64];
__device__ float  g_invf[64];

// ---------------- helpers ----------------
__device__ __forceinline__ float4 ldh4(const __half* p) {
    uint2 u = *(const uint2*)p;
    float2 f0 = __half22float2(*(__half2*)&u.x);
    float2 f1 = __half22float2(*(__half2*)&u.y);
    return make_float4(f0.x, f0.y, f1.x, f1.y);
}
__device__ __forceinline__ void mma_fp16(float* c, const uint32_t* a, const uint32_t* b) {
    asm volatile("mma.sync.aligned.m16n8k16.row.col.f32.f16.f16.f32 "
        "{%0,%1,%2,%3}, {%4,%5,%6,%7}, {%8,%9}, {%0,%1,%2,%3};"
        : "+f"(c[0]), "+f"(c[1]), "+f"(c[2]), "+f"(c[3])
        : "r"(a[0]), "r"(a[1]), "r"(a[2]), "r"(a[3]), "r"(b[0]), "r"(b[1]));
}
__device__ __forceinline__ void cpasync16(uint32_t s, const void* g) {
    asm volatile("cp.async.cg.shared.global [%0], [%1], 16;" :: "r"(s), "l"(g));
}
__device__ __forceinline__ void ldsm_x4(uint32_t* r, uint32_t addr) {
    asm volatile("ldmatrix.sync.aligned.m8n8.x4.shared.b16 {%0,%1,%2,%3}, [%4];"
        : "=r"(r[0]), "=r"(r[1]), "=r"(r[2]), "=r"(r[3]) : "r"(addr));
}
__device__ __forceinline__ void ldsm_x4_t(uint32_t* r, uint32_t addr) {
    asm volatile("ldmatrix.sync.aligned.m8n8.x4.trans.shared.b16 {%0,%1,%2,%3}, [%4];"
        : "=r"(r[0]), "=r"(r[1]), "=r"(r[2]), "=r"(r[3]) : "r"(addr));
}

// ---------------- rmsnorm -> fp16 out ----------------
__global__ void rmsnorm_kernel(const float* __restrict__ x, const float* __restrict__ w,
                               __half* __restrict__ out, float eps) {
    int row = blockIdx.x;
    const float4* xr = (const float4*)(x + (size_t)row * DD);
    float4 v = xr[threadIdx.x];
    float s = v.x * v.x + v.y * v.y + v.z * v.z + v.w * v.w;
    __shared__ float red[8];
    #pragma unroll
    for (int o = 16; o > 0; o >>= 1) s += __shfl_down_sync(0xffffffffu, s, o);
    if ((threadIdx.x & 31) == 0) red[threadIdx.x >> 5] = s;
    __syncthreads();
    if (threadIdx.x < 8) {
        s = red[threadIdx.x];
        #pragma unroll
        for (int o = 4; o > 0; o >>= 1) s += __shfl_down_sync(0xffu, s, o);
        if (threadIdx.x == 0) red[0] = s;
    }
    __syncthreads();
    float inv = rsqrtf(red[0] / (float)DD + eps);
    float4 wv = ((const float4*)w)[threadIdx.x];
    __half2* orow = (__half2*)(out + (size_t)row * DD);
    orow[threadIdx.x * 2]     = __floats2half2_rn(v.x * inv * wv.x, v.y * inv * wv.y);
    orow[threadIdx.x * 2 + 1] = __floats2half2_rn(v.z * inv * wv.z, v.w * inv * wv.w);
}

// ---------------- batched weight convert+transpose ----------------
__global__ void convT5(const float* __restrict__ w0, const float* __restrict__ w1,
                       const float* __restrict__ w2, const float* __restrict__ w3,
                       const float* __restrict__ w4, __half* __restrict__ Wt) {
    __shared__ float tile[32][33];
    const float* W = (blockIdx.z == 0) ? w0 : (blockIdx.z == 1) ? w1 :
                     (blockIdx.z == 2) ? w2 : (blockIdx.z == 3) ? w3 : w4;
    __half* dst = Wt + (size_t)blockIdx.z * 1024 * DD;
    int n0 = blockIdx.x * 32, k0 = blockIdx.y * 32;
    #pragma unroll
    for (int j = threadIdx.y; j < 32; j += 8)
        tile[j][threadIdx.x] = W[(size_t)(k0 + j) * DD + n0 + threadIdx.x];
    __syncthreads();
    #pragma unroll
    for (int j = threadIdx.y; j < 32; j += 8)
        dst[(size_t)(n0 + j) * DD + k0 + threadIdx.x] = __float2half_rn(tile[threadIdx.x][j]);
}
__global__ void convTI(const float* __restrict__ wg, const float* __restrict__ wu,
                       __half* __restrict__ Wt) {
    __shared__ float tile[32][33];
    const float* W = blockIdx.z ? wu : wg;
    int ro = blockIdx.z;
    int n0 = blockIdx.x * 32, k0 = blockIdx.y * 32;
    #pragma unroll
    for (int j = threadIdx.y; j < 32; j += 8)
        tile[j][threadIdx.x] = W[(size_t)(k0 + j) * II + n0 + threadIdx.x];
    __syncthreads();
    #pragma unroll
    for (int j = threadIdx.y; j < 32; j += 8)
        Wt[((size_t)(n0 + j) * 2 + ro) * DD + k0 + threadIdx.x] = __float2half_rn(tile[threadIdx.x][j]);
}
__global__ void convTW(const float* __restrict__ W, __half* __restrict__ Wt) {
    __shared__ float tile[32][33];
    int n0 = blockIdx.x * 32, k0 = blockIdx.y * 32;
    #pragma unroll
    for (int j = threadIdx.y; j < 32; j += 8)
        tile[j][threadIdx.x] = W[(size_t)(k0 + j) * DD + n0 + threadIdx.x];
    __syncthreads();
    #pragma unroll
    for (int j = threadIdx.y; j < 32; j += 8)
        Wt[(size_t)(n0 + j) * II + k0 + threadIdx.x] = __float2half_rn(tile[threadIdx.x][j]);
}

// ================= fp16 tensor-core GEMM =================
#define BKH 64
#define XW 36
#define AW (128*XW)
#define BW (128*XW)
#define STG (AW+BW)
#define SMEM_GEMM (3*STG*4)

template <int MODE>
__global__ __launch_bounds__(256, 2)
void hgemm_t(const __half* __restrict__ A, const __half* __restrict__ Bt,
             const float* __restrict__ R, void* __restrict__ Cv,
             int M, int N, int K) {
    extern __shared__ uint32_t smw[];

    const int tid = threadIdx.x;
    const int lane = tid & 31;
    const int w = tid >> 5;
    const int g = lane >> 2, q = lane & 3;
    const int wm = (w & 1) * 64;
    const int wn = (w >> 1) * 32;
    const int bm = blockIdx.y * 128, bn = blockIdx.x * 128;

    uint32_t sBase = (uint32_t)__cvta_generic_to_shared(smw);

    const uint32_t aLane = (uint32_t)((wm + (lane & 15)) * XW + ((lane >> 4) << 2));
    const uint32_t bLane = (uint32_t)((wn + (lane & 7) + ((lane >> 4) << 3)) * XW + (((lane >> 3) & 1) << 2));

    float acc[4][4][4];
    #pragma unroll
    for (int i = 0; i < 4; ++i)
        #pragma unroll
        for (int j = 0; j < 4; ++j)
            #pragma unroll
            for (int r = 0; r < 4; ++r) acc[i][j][r] = 0.f;

    const int ntile = K / BKH;

    auto loadTile = [&](int t, int s) {
        #pragma unroll
        for (int i = 0; i < 4; ++i) {
            int idx = i * 256 + tid;
            int row = idx >> 3, kc = (idx & 7) * 8;
            cpasync16(sBase + (uint32_t)((s * STG + row * XW) * 4 + kc * 2),
                      A + (size_t)(bm + row) * K + t * BKH + kc);
        }
        #pragma unroll
        for (int i = 0; i < 4; ++i) {
            int idx = i * 256 + tid;
            int n = idx >> 3, kc = (idx & 7) * 8;
            cpasync16(sBase + (uint32_t)((s * STG + AW + n * XW) * 4 + kc * 2),
                      Bt + (size_t)(bn + n) * K + t * BKH + kc);
        }
        asm volatile("cp.async.commit_group;");
    };

    loadTile(0, 0);
    if (ntile > 1) loadTile(1, 1);

    for (int t = 0; t < ntile; ++t) {
        int s = t % 3;
        if (t + 2 < ntile) asm volatile("cp.async.wait_group 1;");
        else               asm volatile("cp.async.wait_group 0;");
        __syncthreads();
        if (t + 2 < ntile) loadTile(t + 2, (t + 2) % 3);

        const uint32_t aOff = sBase + (uint32_t)(s * STG) * 4;
        const uint32_t bOff = sBase + (uint32_t)(s * STG + AW) * 4;
        #pragma unroll
        for (int ks = 0; ks < 4; ++ks) {
            uint32_t a[4][4], b[4][2];
            #pragma unroll
            for (int mt = 0; mt < 4; ++mt)
                ldsm_x4(a[mt], aOff + (aLane + (uint32_t)(mt * 16 * XW + ks * 8)) * 4);
            #pragma unroll
            for (int np = 0; np < 2; ++np) {
                uint32_t bb[4];
                ldsm_x4(bb, bOff + (bLane + (uint32_t)(np * 16 * XW + ks * 8)) * 4);
                b[np * 2][0]     = bb[0];
                b[np * 2][1]     = bb[1];
                b[np * 2 + 1][0] = bb[2];
                b[np * 2 + 1][1] = bb[3];
            }
            #pragma unroll
            for (int mt = 0; mt < 4; ++mt)
                #pragma unroll
                for (int nt = 0; nt < 4; ++nt)
                    mma_fp16(acc[mt][nt], a[mt], b[nt]);
        }
    }

    #pragma unroll
    for (int mt = 0; mt < 4; ++mt) {
        #pragma unroll
        for (int half = 0; half < 2; ++half) {
            int row = bm + wm + mt * 16 + g + half * 8;
            #pragma unroll
            for (int nt = 0; nt < 4; ++nt) {
                float vx = acc[mt][nt][half * 2 + 0];
                float vy = acc[mt][nt][half * 2 + 1];
                if (MODE == 0) {
                    int col = bn + wn + nt * 8 + q * 2;
                    size_t off = (size_t)row * N + col;
                    float* C = (float*)Cv;
                    float2 v2;
                    v2.x = vx; v2.y = vy;
                    if (R) {
                        const float2 rr = *(const float2*)(R + off);
                        v2.x += rr.x; v2.y += rr.y;
                    }
                    *(float2*)(C + off) = v2;
                } else if (MODE == 1) {
                    int col = bn + wn + nt * 8 + q * 2;
                    __half2* C = (__half2*)Cv;
                    C[((size_t)row * N + col) >> 1] = __floats2half2_rn(vx, vy);
                } else {
                    int oc = (bn + wn) / 2 + nt * 4 + q;
                    float r = (vx / (1.f + expf(-vx))) * vy;
                    __half* C = (__half*)Cv;
                    C[(size_t)row * (N >> 1) + oc] = __float2half_rn(r);
                }
            }
        }
    }
}

// ---------------- conv(K=4)+silu+RoPE fused (q,k path) ----------------
__global__ void conv_silu_rope_kernel(const __half* __restrict__ x, const float* __restrict__ w,
                                      __half* __restrict__ y) {
    int idx = blockIdx.x * 256 + threadIdx.x;
    int j4 = idx & 15;
    int h  = (idx >> 4) & 7;
    int t4 = (idx >> 7) & 2047;
    int b  = idx >> 18;
    const float4* w4 = (const float4*)w;
    int d1 = h * 128 + j4 * 4;
    float4 wa[4], wb[4];
    #pragma unroll
    for (int r = 0; r < 4; ++r) { wa[r] = w4[d1 + r]; wb[r] = w4[d1 + 64 + r]; }
    int t0 = t4 * 4;
    float4 xv1[7], xv2[7];
    #pragma unroll
    for (int j = 0; j < 7; ++j) {
        int tt = t0 - 3 + j;
        if (tt >= 0) {
            const __half* p = x + ((size_t)(b * TT + tt)) * 4096 + d1;
            xv1[j] = ldh4(p);
            xv2[j] = ldh4(p + 64);
        } else {
            xv1[j] = make_float4(0.f, 0.f, 0.f, 0.f);
            xv2[j] = make_float4(0.f, 0.f, 0.f, 0.f);
        }
    }
    const float4* cos4 = (const float4*)g_cos;
    const float4* sin4 = (const float4*)g_sin;
    __half2* y2 = (__half2*)y;
    #pragma unroll
    for (int i = 0; i < 4; ++i) {
        float4 a1, a2;
        a1.x = xv1[i].x * wa[0].x + xv1[i+1].x * wa[0].y + xv1[i+2].x * wa[0].z + xv1[i+3].x * wa[0].w;
        a1.y = xv1[i].y * wa[1].x + xv1[i+1].y * wa[1].y + xv1[i+2].y * wa[1].z + xv1[i+3].y * wa[1].w;
        a1.z = xv1[i].z * wa[2].x + xv1[i+1].z * wa[2].y + xv1[i+2].z * wa[2].z + xv1[i+3].z * wa[2].w;
        a1.w = xv1[i].w * wa[3].x + xv1[i+1].w * wa[3].y + xv1[i+2].w * wa[3].z + xv1[i+3].w * wa[3].w;
        a2.x = xv2[i].x * wb[0].x + xv2[i+1].x * wb[0].y + xv2[i+2].x * wb[0].z + xv2[i+3].x * wb[0].w;
        a2.y = xv2[i].y * wb[1].x + xv2[i+1].y * wb[1].y + xv2[i+2].y * wb[1].z + xv2[i+3].y * wb[1].w;
        a2.z = xv2[i].z * wb[2].x + xv2[i+1].z * wb[2].y + xv2[i+2].z * wb[2].z + xv2[i+3].z * wb[2].w;
        a2.w = xv2[i].w * wb[3].x + xv2[i+1].w * wb[3].y + xv2[i+2].w * wb[3].z + xv2[i+3].w * wb[3].w;
        a1.x /= (1.f + expf(-a1.x)); a1.y /= (1.f + expf(-a1.y));
        a1.z /= (1.f + expf(-a1.z)); a1.w /= (1.f + expf(-a1.w));
        a2.x /= (1.f + expf(-a2.x)); a2.y /= (1.f + expf(-a2.y));
        a2.z /= (1.f + expf(-a2.z)); a2.w /= (1.f + expf(-a2.w));
        int t = t0 + i;
        float4 c = cos4[t * 16 + j4];
        float4 s = sin4[t * 16 + j4];
        float4 o1, o2;
        o1.x = a1.x * c.x - a2.x * s.x;  o2.x = a1.x * s.x + a2.x * c.x;
        o1.y = a1.y * c.y - a2.y * s.y;  o2.y = a1.y * s.y + a2.y * c.y;
        o1.z = a1.z * c.z - a2.z * s.z;  o2.z = a1.z * s.z + a2.z * c.z;
        o1.w = a1.w * c.w - a2.w * s.w;  o2.w = a1.w * s.w + a2.w * c.w;
        size_t base1 = (((size_t)(b * TT + t)) * DD + d1) >> 1;
        y2[base1]      = __floats2half2_rn(o1.x, o1.y);
        y2[base1 + 1]  = __floats2half2_rn(o1.z, o1.w);
        y2[base1 + 32] = __floats2half2_rn(o2.x, o2.y);
        y2[base1 + 33] = __floats2half2_rn(o2.z, o2.w);
    }
}

// ---------------- conv(K=4)+silu (v path) ----------------
__global__ void conv_silu_h_kernel(const __half* __restrict__ x, const float* __restrict__ w,
                                   __half* __restrict__ y) {
    int idx = blockIdx.x * 256 + threadIdx.x;
    int d4 = idx & 255;
    int rest = idx >> 8;
    int t4 = rest & (TT / 4 - 1);
    int b = rest >> 11;
    const float4* w4 = (const float4*)w;
    float4 wr0 = w4[d4 * 4 + 0], wr1 = w4[d4 * 4 + 1];
    float4 wr2 = w4[d4 * 4 + 2], wr3 = w4[d4 * 4 + 3];
    int t0 = t4 * 4;
    float4 xv[7];
    #pragma unroll
    for (int j = 0; j < 7; ++j) {
        int tt = t0 - 3 + j;
        xv[j] = (tt >= 0) ? ldh4(x + ((size_t)(b * TT + tt)) * 4096 + d4 * 4)
                          : make_float4(0.f, 0.f, 0.f, 0.f);
    }
    __half2* y2 = (__half2*)y;
    #pragma unroll
    for (int i = 0; i < 4; ++i) {
        float4 a;
        a.x = xv[i].x * wr0.x + xv[i+1].x * wr0.y + xv[i+2].x * wr0.z + xv[i+3].x * wr0.w;
        a.y = xv[i].y * wr1.x + xv[i+1].y * wr1.y + xv[i+2].y * wr1.z + xv[i+3].y * wr1.w;
        a.z = xv[i].z * wr2.x + xv[i+1].z * wr2.y + xv[i+2].z * wr2.z + xv[i+3].z * wr2.w;
        a.w = xv[i].w * wr3.x + xv[i+1].w * wr3.y + xv[i+2].w * wr3.z + xv[i+3].w * wr3.w;
        a.x /= (1.f + expf(-a.x)); a.y /= (1.f + expf(-a.y));
        a.z /= (1.f + expf(-a.z)); a.w /= (1.f + expf(-a.w));
        size_t bh = ((size_t)(b * TT + t0 + i)) * 512 + d4 * 2;
        y2[bh]     = __floats2half2_rn(a.x, a.y);
        y2[bh + 1] = __floats2half2_rn(a.z, a.w);
    }
}

// ---------------- RoPE tables (cheap FP64: only range reduction) ----------------
__global__ void rope_invf_kernel() {
    int j = threadIdx.x;
    if (j < 64) g_invf[j] = (float)(1.0 / pow(10000.0, (double)j / 64.0));
}
__global__ void rope_table_kernel() {
    int idx = blockIdx.x * 256 + threadIdx.x;
    if (idx >= TT * 64) return;
    int t = idx >> 6, j = idx & 63;
    float f = (float)t * g_invf[j];                 // fp32 phase, same rounding as reference
    double d = (double)f;
    double n = floor(d * 0.15915494309189535);      // 1/(2*pi)
    float r = (float)(d - n * 6.283185307179586);   // reduced to [0, 2*pi)
    float s, c;
    __sincosf(r, &s, &c);
    g_cos[idx] = c;
    g_sin[idx] = s;
}

// ================= retention phase 1 (HMMA): S = (k*dec)^T @ v =================
#define RSTR 136
#define SMEM_P1 ((64*RSTR + 64*RSTR) * 2)
__global__ __launch_bounds__(256, 2)
void ret_phase1(const __half* __restrict__ k, const __half* __restrict__ v,
                __half* __restrict__ S) {
    extern __shared__ __half smh[];
    __half* ks = smh;
    __half* vs = smh + 64 * RSTR;
    int c = blockIdx.x, h = blockIdx.y, b = blockIdx.z;
    float gamma = 1.f - exp2f(-5.f - (float)h);
    float lg = logf(gamma);
    int tid = threadIdx.x, lane = tid & 31, w = tid >> 5;
    int g = lane >> 2, q = lane & 3;
    uint32_t sk = (uint32_t)__cvta_generic_to_shared(ks);
    uint32_t sv = (uint32_t)__cvta_generic_to_shared(vs);

    #pragma unroll
    for (int it = 0; it < 4; ++it) {
        int x = it * 256 + tid;
        int row = x >> 4, ch = x & 15;
        cpasync16(sv + (uint32_t)(row * RSTR + ch * 8) * 2,
                  v + ((size_t)(b * TT + c * 64 + row) * DD + h * 128 + ch * 8));
    }
    asm volatile("cp.async.commit_group;");
    const __half2* k2 = (const __half2*)k;
    for (int x = tid; x < 4096; x += 256) {
        int row = x >> 6, d2 = x & 63;
        float dec = expf(lg * (float)(63 - row));
        float2 kf = __half22float2(k2[((size_t)(b * TT + c * 64 + row) * DD + h * 128) / 2 + d2]);
        *(__half2*)(ks + row * RSTR + d2 * 2) = __floats2half2_rn(kf.x * dec, kf.y * dec);
    }
    asm volatile("cp.async.wait_group 0;");
    __syncthreads();

    int m0 = (w & 3) * 32;
    int e0w = (w >> 2) * 64;
    float acc[2][8][4];
    #pragma unroll
    for (int i = 0; i < 2; ++i)
        #pragma unroll
        for (int j = 0; j < 8; ++j)
            #pragma unroll
            for (int r = 0; r < 4; ++r) acc[i][j][r] = 0.f;

    int aRow = (lane & 7) + ((lane >> 4) << 3);
    int aCol = ((lane >> 3) & 1) << 3;
    int bRow = (lane & 7) + (((lane >> 3) & 1) << 3);
    int bCol = (lane >> 4) << 3;

    #pragma unroll
    for (int kt = 0; kt < 4; ++kt) {
        int j0 = kt * 16;
        uint32_t a[2][4];
        #pragma unroll
        for (int mt = 0; mt < 2; ++mt)
            ldsm_x4_t(a[mt], sk + (uint32_t)((j0 + aRow) * RSTR + m0 + mt * 16 + aCol) * 2);
        #pragma unroll
        for (int np = 0; np < 4; ++np) {
            uint32_t bb[4];
            ldsm_x4_t(bb, sv + (uint32_t)((j0 + bRow) * RSTR + e0w + np * 16 + bCol) * 2);
            #pragma unroll
            for (int mt = 0; mt < 2; ++mt) {
                mma_fp16(acc[mt][np * 2],     a[mt], bb);
                mma_fp16(acc[mt][np * 2 + 1], a[mt], bb + 2);
            }
        }
    }

    size_t sb = (((size_t)(b * HH + h)) * NC + c) * 16384;
    __half2* S2 = (__half2*)S;
    #pragma unroll
    for (int mt = 0; mt < 2; ++mt) {
        #pragma unroll
        for (int nt = 0; nt < 8; ++nt) {
            int e = e0w + nt * 8 + q * 2;
            int d1 = m0 + mt * 16 + g;
            S2[(sb + (size_t)d1 * 128 + e) >> 1]       = __floats2half2_rn(acc[mt][nt][0], acc[mt][nt][1]);
            S2[(sb + (size_t)(d1 + 8) * 128 + e) >> 1] = __floats2half2_rn(acc[mt][nt][2], acc[mt][nt][3]);
        }
    }
}

// ---------------- retention phase 2: parallel exclusive scan (half2) ----------------
__global__ void ret_scan(__half* __restrict__ S) {
    int bh = blockIdx.x >> 5;
    int pairIdx = ((blockIdx.x & 31) << 8) + threadIdx.x;
    int h = bh & 7;
    float gamma = 1.f - exp2f(-5.f - (float)h);
    float cdec = expf(logf(gamma) * 64.f);
    float2 carry = make_float2(0.f, 0.f);
    __half2* S2 = (__half2*)S;
    size_t base = (size_t)bh * NC * 8192 + pairIdx;
    for (int c = 0; c < NC; ++c) {
        size_t idx = base + (size_t)c * 8192;
        float2 loc = __half22float2(S2[idx]);
        S2[idx] = __floats2half2_rn(carry.x, carry.y);
        carry.x = carry.x * cdec + loc.x;
        carry.y = carry.y * cdec + loc.y;
    }
}

// ================= retention phase 3 (HMMA) + fused gate =================
#define ASTR3 72
#define SMEM_P3 ((3*64*RSTR + 64*ASTR3) * 2 + 512)
__global__ __launch_bounds__(256, 2)
void ret_phase3(const __half* __restrict__ q, const __half* __restrict__ k,
                const __half* __restrict__ v, const __half* __restrict__ S,
                const __half* __restrict__ gbig, const float* __restrict__ gnw,
                __half* __restrict__ oh) {
    extern __shared__ __half smh[];
    __half* qs  = smh;
    __half* ksb = smh + 64 * RSTR;
    __half* vsb = smh + 2 * 64 * RSTR;
    __half* ats = smh + 3 * 64 * RSTR;
    float*  rn  = (float*)(smh + 3 * 64 * RSTR + 64 * ASTR3);
    int c = blockIdx.x, h = blockIdx.y, b = blockIdx.z;
    float gamma = 1.f - exp2f(-5.f - (float)h);
    float lg = logf(gamma);
    const float scale = 0.08838834764831845f;
    int tid = threadIdx.x, lane = tid & 31, w = tid >> 5;
    int g = lane >> 2, qq = lane & 3;
    uint32_t sq = (uint32_t)__cvta_generic_to_shared(qs);
    uint32_t sk = (uint32_t)__cvta_generic_to_shared(ksb);
    uint32_t sv = (uint32_t)__cvta_generic_to_shared(vsb);
    uint32_t sa = (uint32_t)__cvta_generic_to_shared(ats);

    #pragma unroll
    for (int it = 0; it < 4; ++it) {
        int x = it * 256 + tid;
        int row = x >> 4, ch = x & 15;
        size_t gg = (size_t)(b * TT + c * 64 + row) * DD + h * 128 + ch * 8;
        uint32_t off = (uint32_t)(row * RSTR + ch * 8) * 2;
        cpasync16(sq + off, q + gg);
        cpasync16(sk + off, k + gg);
        cpasync16(sv + off, v + gg);
    }
    asm volatile("cp.async.commit_group;");
    asm volatile("cp.async.wait_group 0;");
    __syncthreads();

    const int mt = w & 3;
    const int m0 = mt * 16;
    const int eh = w >> 2;
    size_t sbg = (((size_t)(b * HH + h)) * NC + c) * 16384;

    int aRow = m0 + (lane & 15);
    int aCol = (lane >> 4) << 3;
    int bRowN = (lane & 7) + ((lane >> 4) << 3);
    int bColN = ((lane >> 3) & 1) << 3;
    int tRow = (lane & 7) + (((lane >> 3) & 1) << 3);
    int tCol = (lane >> 4) << 3;

    // Step A: att = q @ k^T
    {
        int n0 = eh * 32;
        float accT[4][4];
        #pragma unroll
        for (int i = 0; i < 4; ++i)
            #pragma unroll
            for (int r = 0; r < 4; ++r) accT[i][r] = 0.f;
        #pragma unroll
        for (int kt = 0; kt < 8; ++kt) {
            uint32_t a[4];
            ldsm_x4(a, sq + (uint32_t)(aRow * RSTR + aCol + kt * 16) * 2);
            #pragma unroll
            for (int np = 0; np < 2; ++np) {
                uint32_t bb[4];
                ldsm_x4(bb, sk + (uint32_t)((n0 + np * 16 + bRowN) * RSTR + bColN + kt * 16) * 2);
                mma_fp16(accT[np * 2],     a, bb);
                mma_fp16(accT[np * 2 + 1], a, bb + 2);
            }
        }
        #pragma unroll
        for (int nt = 0; nt < 4; ++nt) {
            int j0 = n0 + nt * 8 + qq * 2;
            int i1 = m0 + g, i2 = i1 + 8;
            float f0 = (i1 >= j0)     ? scale * expf(lg * (float)(i1 - j0))     : 0.f;
            float f1 = (i1 >= j0 + 1) ? scale * expf(lg * (float)(i1 - j0 - 1)) : 0.f;
            float f2 = (i2 >= j0)     ? scale * expf(lg * (float)(i2 - j0))     : 0.f;
            float f3 = (i2 >= j0 + 1) ? scale * expf(lg * (float)(i2 - j0 - 1)) : 0.f;
            *(__half2*)(ats + i1 * ASTR3 + j0) = __floats2half2_rn(accT[nt][0] * f0, accT[nt][1] * f1);
            *(__half2*)(ats + i2 * ASTR3 + j0) = __floats2half2_rn(accT[nt][2] * f2, accT[nt][3] * f3);
        }
    }
    __syncthreads();

    #pragma unroll
    for (int it = 0; it < 4; ++it) {
        int x = it * 256 + tid;
        int row = x >> 4, ch = x & 15;
        cpasync16(sk + (uint32_t)(row * RSTR + ch * 8) * 2, S + sbg + (size_t)row * 128 + ch * 8);
    }
    asm volatile("cp.async.commit_group;");

    // Step B: o1 = att @ v
    const int e0w = eh * 64;
    float accA[8][4];
    #pragma unroll
    for (int i = 0; i < 8; ++i)
        #pragma unroll
        for (int r = 0; r < 4; ++r) accA[i][r] = 0.f;
    #pragma unroll
    for (int kt = 0; kt < 4; ++kt) {
        int j0 = kt * 16;
        uint32_t a[4];
        ldsm_x4(a, sa + (uint32_t)(aRow * ASTR3 + aCol + kt * 16) * 2);
        #pragma unroll
        for (int np = 0; np < 4; ++np) {
            uint32_t bb[4];
            ldsm_x4_t(bb, sv + (uint32_t)((j0 + tRow) * RSTR + e0w + np * 16 + tCol) * 2);
            mma_fp16(accA[np * 2],     a, bb);
            mma_fp16(accA[np * 2 + 1], a, bb + 2);
        }
    }
    asm volatile("cp.async.wait_group 0;");
    __syncthreads();

    #pragma unroll
    for (int it = 0; it < 4; ++it) {
        int x = it * 256 + tid;
        int row = x >> 4, ch = x & 15;
        cpasync16(sv + (uint32_t)(row * RSTR + ch * 8) * 2, S + sbg + (size_t)(64 + row) * 128 + ch * 8);
    }
    asm volatile("cp.async.commit_group;");

    // Step C1: accB += q @ S[0:64]
    float accB[8][4];
    #pragma unroll
    for (int i = 0; i < 8; ++i)
        #pragma unroll
        for (int r = 0; r < 4; ++r) accB[i][r] = 0.f;
    #pragma unroll
    for (int kt = 0; kt < 4; ++kt) {
        int d0 = kt * 16;
        uint32_t a[4];
        ldsm_x4(a, sq + (uint32_t)(aRow * RSTR + aCol + kt * 16) * 2);
        #pragma unroll
        for (int np = 0; np < 4; ++np) {
            uint32_t bb[4];
            ldsm_x4_t(bb, sk + (uint32_t)((d0 + tRow) * RSTR + e0w + np * 16 + tCol) * 2);
            mma_fp16(accB[np * 2],     a, bb);
            mma_fp16(accB[np * 2 + 1], a, bb + 2);
        }
    }
    asm volatile("cp.async.wait_group 0;");
    __syncthreads();

    // Step C2: accB += q @ S[64:128]
    #pragma unroll
    for (int kt = 4; kt < 8; ++kt) {
        int d0 = (kt - 4) * 16;
        uint32_t a[4];
        ldsm_x4(a, sq + (uint32_t)(aRow * RSTR + aCol + kt * 16) * 2);
        #pragma unroll
        for (int np = 0; np < 4; ++np) {
            uint32_t bb[4];
            ldsm_x4_t(bb, sv + (uint32_t)((d0 + tRow) * RSTR + e0w + np * 16 + tCol) * 2);
            mma_fp16(accB[np * 2],     a, bb);
            mma_fp16(accB[np * 2 + 1], a, bb + 2);
        }
    }

    // combine + fused rmsnorm(128) * gnw * silu(g) -> fp16 oh
    int i1 = m0 + g;
    int i2 = i1 + 8;
    float cf1 = scale * expf(lg * (float)(i1 + 1));
    float cf2 = scale * expf(lg * (float)(i1 + 9));
    float ss1 = 0.f, ss2 = 0.f;
    #pragma unroll
    for (int nt = 0; nt < 8; ++nt) {
        accA[nt][0] += cf1 * accB[nt][0];
        accA[nt][1] += cf1 * accB[nt][1];
        accA[nt][2] += cf2 * accB[nt][2];
        accA[nt][3] += cf2 * accB[nt][3];
        ss1 += accA[nt][0] * accA[nt][0] + accA[nt][1] * accA[nt][1];
        ss2 += accA[nt][2] * accA[nt][2] + accA[nt][3] * accA[nt][3];
    }
    ss1 += __shfl_xor_sync(0xffffffffu, ss1, 1);
    ss1 += __shfl_xor_sync(0xffffffffu, ss1, 2);
    ss2 += __shfl_xor_sync(0xffffffffu, ss2, 1);
    ss2 += __shfl_xor_sync(0xffffffffu, ss2, 2);
    if (qq == 0) { rn[eh * 64 + i1] = ss1; rn[eh * 64 + i2] = ss2; }
    __syncthreads();
    float inv1 = rsqrtf((rn[i1] + rn[64 + i1]) * 0.0078125f + GATE_EPS);
    float inv2 = rsqrtf((rn[i2] + rn[64 + i2]) * 0.0078125f + GATE_EPS);

    size_t r1 = (size_t)(b * TT + c * 64 + i1);
    size_t r2 = r1 + 8;
    __half2* dst = (__half2*)oh;
    #pragma unroll
    for (int nt = 0; nt < 8; ++nt) {
        int e = e0w + nt * 8 + qq * 2;
        float2 gw = *(const float2*)(gnw + e);
        float2 g1 = __half22float2(*(const __half2*)(gbig + r1 * 4096 + 3072 + h * 128 + e));
        float2 g2 = __half22float2(*(const __half2*)(gbig + r2 * 4096 + 3072 + h * 128 + e));
        float o1x = accA[nt][0] * inv1 * gw.x * (g1.x / (1.f + expf(-g1.x)));
        float o1y = accA[nt][1] * inv1 * gw.y * (g1.y / (1.f + expf(-g1.y)));
        float o2x = accA[nt][2] * inv2 * gw.x * (g2.x / (1.f + expf(-g2.x)));
        float o2y = accA[nt][3] * inv2 * gw.y * (g2.y / (1.f + expf(-g2.y)));
        dst[(r1 * 1024 + h * 128 + e) >> 1] = __floats2half2_rn(o1x, o1y);
        dst[(r2 * 1024 + h * 128 + e) >> 1] = __floats2half2_rn(o2x, o2y);
    }
}

// ---------------- launch ----------------
extern "C" void kernel_launch(void* const* d_in, const int* in_sizes, int n_in,
                              void* d_out, int out_size) {
    const float* hs    = (const float*)d_in[0];
    const float* ln1   = (const float*)d_in[1];
    const float* ln2   = (const float*)d_in[2];
    const float* wq    = (const float*)d_in[3];
    const float* wk    = (const float*)d_in[4];
    const float* wv    = (const float*)d_in[5];
    const float* wg    = (const float*)d_in[6];
    const float* wo    = (const float*)d_in[7];
    const float* cq    = (const float*)d_in[8];
    const float* ck    = (const float*)d_in[9];
    const float* cv    = (const float*)d_in[10];
    const float* gn    = (const float*)d_in[11];
    const float* wgate = (const float*)d_in[12];
    const float* wup   = (const float*)d_in[13];
    const float* wdown = (const float*)d_in[14];
    float* out = (float*)d_out;

    cudaFuncSetAttribute(hgemm_t<0>, cudaFuncAttributeMaxDynamicSharedMemorySize, SMEM_GEMM);
    cudaFuncSetAttribute(hgemm_t<1>, cudaFuncAttributeMaxDynamicSharedMemorySize, SMEM_GEMM);
    cudaFuncSetAttribute(hgemm_t<2>, cudaFuncAttributeMaxDynamicSharedMemorySize, SMEM_GEMM);
    cudaFuncSetAttribute(ret_phase1, cudaFuncAttributeMaxDynamicSharedMemorySize, SMEM_P1);
    cudaFuncSetAttribute(ret_phase3, cudaFuncAttributeMaxDynamicSharedMemorySize, SMEM_P3);

    float *hbuf;
    __half *big, *qh, *kh, *vh, *Sh, *xh, *oh, *m1h, *bt;
    cudaGetSymbolAddress((void**)&big, g_big);
    cudaGetSymbolAddress((void**)&qh,  g_qh);
    cudaGetSymbolAddress((void**)&kh,  g_kh);
    cudaGetSymbolAddress((void**)&vh,  g_vh);
    cudaGetSymbolAddress((void**)&hbuf, g_h);
    cudaGetSymbolAddress((void**)&Sh,  g_Sh);
    cudaGetSymbolAddress((void**)&xh,  g_xh);
    cudaGetSymbolAddress((void**)&oh,  g_oh);
    cudaGetSymbolAddress((void**)&m1h, g_m1h);
    cudaGetSymbolAddress((void**)&bt,  g_bt);

    __half* bt_wo   = bt + (size_t)4096 * DD;
    __half* bt_mlp  = bt + (size_t)5120 * DD;
    __half* bt_down = bt + (size_t)10752 * DD;

    dim3 tb(32, 8);
    convT5<<<dim3(32, 32, 5), tb>>>(wq, wk, wv, wg, wo, bt);
    convTI<<<dim3(88, 32, 2), tb>>>(wgate, wup, bt_mlp);
    convTW<<<dim3(32, 88, 1), tb>>>(wdown, bt_down);

    rope_invf_kernel<<<1, 64>>>();
    rope_table_kernel<<<(TT * 64 + 255) / 256, 256>>>();
    rmsnorm_kernel<<<BT, 256>>>(hs, ln1, xh, RMS_EPS);

    dim3 gQKVG(4096 / 128, BT / 128);
    hgemm_t<1><<<gQKVG, 256, SMEM_GEMM>>>(xh, bt, nullptr, big, BT, 4096, DD);

    const int crblocks = (BB * (TT / 4) * HH * 16) / 256;
    const int cvblocks = BB * TT / 4;
    conv_silu_rope_kernel<<<crblocks, 256>>>(big,        cq, qh);
    conv_silu_rope_kernel<<<crblocks, 256>>>(big + 1024, ck, kh);
    conv_silu_h_kernel<<<cvblocks, 256>>>(big + 2048, cv, vh);

    dim3 gc(NC, HH, BB);
    ret_phase1<<<gc, 256, SMEM_P1>>>(kh, vh, Sh);
    ret_scan<<<BB * HH * 32, 256>>>(Sh);
    ret_phase3<<<gc, 256, SMEM_P3>>>(qh, kh, vh, Sh, big, gn, oh);

    dim3 gD(DD / 128, BT / 128);
    hgemm_t<0><<<gD, 256, SMEM_GEMM>>>(oh, bt_wo, hs, hbuf, BT, DD, DD);

    rmsnorm_kernel<<<BT, 256>>>(hbuf, ln2, xh, RMS_EPS);
    dim3 gMLP(5632 / 128, BT / 128);
    hgemm_t<2><<<gMLP, 256, SMEM_GEMM>>>(xh, bt_mlp, nullptr, m1h, BT, 5632, DD);
    hgemm_t<0><<<gD, 256, SMEM_GEMM>>>(m1h, bt_down, hbuf, out, BT, DD, II);
}